// round 1
// baseline (speedup 1.0000x reference)
#include <cuda_runtime.h>

#define BB 4
#define TT 4096
#define CC 1024
#define HH 16
#define GG 8
#define HSD 64
#define GTT 512

// ---- scratch (static device globals; no runtime allocation allowed) ----
__device__ float g_qkv[(size_t)BB*TT*3*CC];        // 192 MB
__device__ float g_qa[(size_t)BB*HH*GG*GTT*HSD];   // 64 MB
__device__ float g_ka[(size_t)BB*HH*GG*GTT*HSD];
__device__ float g_va[(size_t)BB*HH*GG*GTT*HSD];
__device__ float g_ob[(size_t)BB*TT*CC];           // 64 MB

// =================== SGEMM (fp32, 128x128x8, 8x8/thread) ===================
#define GBM 128
#define GBN 128
#define GBK 8
#define ASP 132   // padded A-tile stride (conflict-free transposed stores)

__global__ __launch_bounds__(256, 2) void sgemm_k(
    const float* __restrict__ A, const float* __restrict__ B,
    float* __restrict__ Cm, int M, int N, int K)
{
    __shared__ float As[GBK * ASP];
    __shared__ float Bs[GBK * GBN];
    int tid = threadIdx.x;
    int tr = tid >> 4, tc = tid & 15;
    int arow = tid >> 1;
    int acol = (tid & 1) << 2;
    int brow = tid >> 5;
    int bcol = (tid & 31) << 2;
    const float* Ab = A + (size_t)blockIdx.y * GBM * K;
    const float* Bb = B + (size_t)blockIdx.x * GBN;
    float acc[8][8] = {};
    for (int k0 = 0; k0 < K; k0 += GBK) {
        float4 av = *(const float4*)(Ab + (size_t)arow * K + k0 + acol);
        As[(acol + 0) * ASP + arow] = av.x;
        As[(acol + 1) * ASP + arow] = av.y;
        As[(acol + 2) * ASP + arow] = av.z;
        As[(acol + 3) * ASP + arow] = av.w;
        *(float4*)(Bs + brow * GBN + bcol) =
            *(const float4*)(Bb + (size_t)(k0 + brow) * N + bcol);
        __syncthreads();
        #pragma unroll
        for (int kk = 0; kk < GBK; kk++) {
            float ar[8], br[8];
            *(float4*)(ar)     = *(float4*)(As + kk * ASP + tr * 8);
            *(float4*)(ar + 4) = *(float4*)(As + kk * ASP + tr * 8 + 4);
            *(float4*)(br)     = *(float4*)(Bs + kk * GBN + tc * 8);
            *(float4*)(br + 4) = *(float4*)(Bs + kk * GBN + tc * 8 + 4);
            #pragma unroll
            for (int i = 0; i < 8; i++)
                #pragma unroll
                for (int j = 0; j < 8; j++)
                    acc[i][j] = fmaf(ar[i], br[j], acc[i][j]);
        }
        __syncthreads();
    }
    float* Cb = Cm + (size_t)blockIdx.y * GBM * N + (size_t)blockIdx.x * GBN;
    #pragma unroll
    for (int i = 0; i < 8; i++) {
        #pragma unroll
        for (int j = 0; j < 8; j += 4) {
            float4 v = make_float4(acc[i][j], acc[i][j+1], acc[i][j+2], acc[i][j+3]);
            *(float4*)(Cb + (size_t)(tr * 8 + i) * N + tc * 8 + j) = v;
        }
    }
}

// =================== RoPE + grouped scatter ===================
// flat id = ((b*H + h)*T + t)*32 + j ; one thread = one rotation pair for q & k, plus v copy
__global__ __launch_bounds__(256) void rope_k(
    const float* __restrict__ fcos, const float* __restrict__ fsin)
{
    unsigned id = blockIdx.x * 256u + threadIdx.x;
    int j = id & 31;
    int t = (id >> 5) & (TT - 1);
    int h = (id >> 17) & (HH - 1);
    int b = id >> 21;
    const float* row = g_qkv + (size_t)(b * TT + t) * (3 * CC);
    float2 qv = *(const float2*)(row + h * HSD + 2 * j);
    float2 kv = *(const float2*)(row + CC + h * HSD + 2 * j);
    float2 vv = *(const float2*)(row + 2 * CC + h * HSD + 2 * j);
    float c = fcos[t * 32 + j];
    float s = fsin[t * 32 + j];
    float2 qo = make_float2(qv.x * c - qv.y * s, qv.x * s + qv.y * c);
    float2 ko = make_float2(kv.x * c - kv.y * s, kv.x * s + kv.y * c);
    // q/k grouped view scramble: h2 = t&15, g = h>>1, gt = (h&1)*256 + (t>>4)
    int h2 = t & 15;
    int gq = h >> 1;
    int gtq = ((h & 1) << 8) | (t >> 4);
    size_t qidx = (((size_t)((b * HH + h2) * GG + gq) * GTT + gtq) * HSD) + 2 * j;
    *(float2*)(g_qa + qidx) = qo;
    *(float2*)(g_ka + qidx) = ko;
    // v natural grouping: g = t>>9, gt = t&511
    int gv = t >> 9, gtv = t & 511;
    size_t vidx = (((size_t)((b * HH + h) * GG + gv) * GTT + gtv) * HSD) + 2 * j;
    *(float2*)(g_va + vidx) = vv;
}

// =================== Block-local causal flash attention ===================
#define PADA 68
#define ATT_SMEM ((4 * 64 * PADA + 3 * 64) * sizeof(float))

__global__ __launch_bounds__(256) void attn_k() {
    extern __shared__ float sm[];
    float* Qs = sm;                     // [d][q], scaled by 1/8
    float* Ks = sm + 64 * PADA;         // [d][j]
    float* Vs = sm + 2 * 64 * PADA;     // [j][hs]
    float* Pb = sm + 3 * 64 * PADA;     // [j][q]  (scores, then probs)
    float* mrow = sm + 4 * 64 * PADA;
    float* lrow = mrow + 64;
    float* crow = mrow + 128;

    int bx = blockIdx.x;
    int qt = bx & 7;
    int g  = (bx >> 3) & 7;
    int h  = (bx >> 6) & 15;
    int b  = bx >> 10;
    size_t base = ((size_t)((b * HH + h) * GG + g)) * GTT * HSD;
    const float* Qb = g_qa + base;
    const float* Kb = g_ka + base;
    const float* Vb = g_va + base;

    int tid = threadIdx.x;
    int tr = tid >> 4, tc = tid & 15;
    int lq  = tid & 15;
    int ld4 = (tid >> 4) << 2;

    #pragma unroll
    for (int it = 0; it < 4; it++) {
        int q = lq + it * 16;
        float4 v = *(const float4*)(Qb + (size_t)(qt * 64 + q) * HSD + ld4);
        Qs[(ld4 + 0) * PADA + q] = v.x * 0.125f;
        Qs[(ld4 + 1) * PADA + q] = v.y * 0.125f;
        Qs[(ld4 + 2) * PADA + q] = v.z * 0.125f;
        Qs[(ld4 + 3) * PADA + q] = v.w * 0.125f;
    }
    if (tid < 64) { mrow[tid] = -3.0e38f; lrow[tid] = 0.f; crow[tid] = 0.f; }

    float oacc[4][4] = {};

    for (int kt = 0; kt <= qt; kt++) {
        __syncthreads();
        #pragma unroll
        for (int it = 0; it < 4; it++) {
            int jj = lq + it * 16;
            float4 kv = *(const float4*)(Kb + (size_t)(kt * 64 + jj) * HSD + ld4);
            Ks[(ld4 + 0) * PADA + jj] = kv.x;
            Ks[(ld4 + 1) * PADA + jj] = kv.y;
            Ks[(ld4 + 2) * PADA + jj] = kv.z;
            Ks[(ld4 + 3) * PADA + jj] = kv.w;
            float4 vv = *(const float4*)(Vb + (size_t)(kt * 64 + jj) * HSD + ld4);
            *(float4*)(Vs + jj * PADA + ld4) = vv;
        }
        __syncthreads();
        // S = Q K^T  (each thread 4x4 of 64x64)
        float sacc[4][4] = {};
        #pragma unroll
        for (int kk = 0; kk < 64; kk++) {
            float4 a  = *(float4*)(Qs + kk * PADA + tr * 4);
            float4 bv = *(float4*)(Ks + kk * PADA + tc * 4);
            float ar[4] = {a.x, a.y, a.z, a.w};
            float br[4] = {bv.x, bv.y, bv.z, bv.w};
            #pragma unroll
            for (int i = 0; i < 4; i++)
                #pragma unroll
                for (int j = 0; j < 4; j++)
                    sacc[i][j] = fmaf(ar[i], br[j], sacc[i][j]);
        }
        bool diag = (kt == qt);
        #pragma unroll
        for (int i = 0; i < 4; i++)
            #pragma unroll
            for (int j = 0; j < 4; j++) {
                float sv = sacc[i][j];
                if (diag && (tc * 4 + j) > (tr * 4 + i)) sv = -1e30f;
                Pb[(tc * 4 + j) * PADA + tr * 4 + i] = sv;
            }
        __syncthreads();
        // online softmax: warp w owns rows w*8..w*8+7
        {
            int warp = tid >> 5, lane = tid & 31;
            #pragma unroll
            for (int r = 0; r < 8; r++) {
                int q = warp * 8 + r;
                float s1 = Pb[lane * PADA + q];
                float s2 = Pb[(lane + 32) * PADA + q];
                float mx = fmaxf(s1, s2);
                #pragma unroll
                for (int off = 16; off > 0; off >>= 1)
                    mx = fmaxf(mx, __shfl_xor_sync(0xffffffffu, mx, off));
                float mold = mrow[q];
                float mnew = fmaxf(mold, mx);
                float p1 = __expf(s1 - mnew);
                float p2 = __expf(s2 - mnew);
                float ps = p1 + p2;
                #pragma unroll
                for (int off = 16; off > 0; off >>= 1)
                    ps += __shfl_xor_sync(0xffffffffu, ps, off);
                if (lane == 0) {
                    float corr = __expf(mold - mnew);
                    crow[q] = corr;
                    lrow[q] = lrow[q] * corr + ps;
                    mrow[q] = mnew;
                }
                Pb[lane * PADA + q] = p1;
                Pb[(lane + 32) * PADA + q] = p2;
            }
        }
        __syncthreads();
        // rescale + O += P V
        float cr[4];
        #pragma unroll
        for (int i = 0; i < 4; i++) cr[i] = crow[tr * 4 + i];
        #pragma unroll
        for (int i = 0; i < 4; i++)
            #pragma unroll
            for (int j = 0; j < 4; j++) oacc[i][j] *= cr[i];
        #pragma unroll
        for (int kk = 0; kk < 64; kk++) {
            float4 a  = *(float4*)(Pb + kk * PADA + tr * 4);
            float4 bv = *(float4*)(Vs + kk * PADA + tc * 4);
            float ar[4] = {a.x, a.y, a.z, a.w};
            float br[4] = {bv.x, bv.y, bv.z, bv.w};
            #pragma unroll
            for (int i = 0; i < 4; i++)
                #pragma unroll
                for (int j = 0; j < 4; j++)
                    oacc[i][j] = fmaf(ar[i], br[j], oacc[i][j]);
        }
    }
    __syncthreads();
    // epilogue: normalize, un-group (row tau = g*512 + qt*64 + q, col h*64 + hs)
    size_t rowbase = (size_t)b * TT + g * GTT + qt * 64;
    #pragma unroll
    for (int i = 0; i < 4; i++) {
        float linv = 1.0f / lrow[tr * 4 + i];
        float4 v = make_float4(oacc[i][0] * linv, oacc[i][1] * linv,
                               oacc[i][2] * linv, oacc[i][3] * linv);
        *(float4*)(g_ob + (rowbase + tr * 4 + i) * CC + h * HSD + tc * 4) = v;
    }
}

// =================== Pooling (qb/kb/vb; L=1 attention is identity) ===================
__global__ __launch_bounds__(64) void pool_k(
    const float* __restrict__ qp, const float* __restrict__ kp,
    const float* __restrict__ vp, float* __restrict__ out)
{
    int bx = blockIdx.x;           // [0, 3*448)
    int which = bx / 448;          // 0=qb, 1=kb, 2=vb
    int rem = bx - which * 448;
    int g = rem % 7;
    int bh = rem / 7;              // b*16 + h
    const float* src = (which == 0 ? g_qa : (which == 1 ? g_ka : g_va))
                     + ((size_t)bh * GG + g) * GTT * HSD;
    const float* proj = (which == 0 ? qp : (which == 1 ? kp : vp));
    int hs = threadIdx.x;
    float acc = 0.f;
    #pragma unroll 8
    for (int t = 0; t < GTT; t++)
        acc = fmaf(src[(size_t)t * HSD + hs], proj[t], acc);
    out[(size_t)BB * TT * CC + (size_t)which * (BB * HH * 7 * HSD)
        + (size_t)(bh * 7 + g) * HSD + hs] = acc;
}

// =================== launch ===================
extern "C" void kernel_launch(void* const* d_in, const int* in_sizes, int n_in,
                              void* d_out, int out_size) {
    (void)in_sizes; (void)n_in; (void)out_size;
    const float* x    = (const float*)d_in[0];
    const float* Wqkv = (const float*)d_in[1];
    const float* Wo   = (const float*)d_in[2];
    const float* qp   = (const float*)d_in[3];
    const float* kp   = (const float*)d_in[4];
    const float* vp   = (const float*)d_in[5];
    const float* fc   = (const float*)d_in[6];
    const float* fs   = (const float*)d_in[7];
    float* out = (float*)d_out;

    float *qkv_p, *ob_p;
    cudaGetSymbolAddress((void**)&qkv_p, g_qkv);
    cudaGetSymbolAddress((void**)&ob_p, g_ob);
    cudaFuncSetAttribute(attn_k, cudaFuncAttributeMaxDynamicSharedMemorySize,
                         (int)ATT_SMEM);

    // 1) qkv = x @ Wqkv
    dim3 g1(3 * CC / GBN, BB * TT / GBM);
    sgemm_k<<<g1, 256>>>(x, Wqkv, qkv_p, BB * TT, 3 * CC, CC);
    // 2) rope + grouped scatter
    rope_k<<<(BB * HH * TT * 32) / 256, 256>>>(fc, fs);
    // 3) block-local causal attention
    attn_k<<<BB * HH * GG * 8, 256, ATT_SMEM>>>();
    // 4) qb/kb/vb pools (writes tail of d_out)
    pool_k<<<3 * BB * HH * 7, 64>>>(qp, kp, vp, out);
    // 5) out = o @ Wo (writes head of d_out)
    dim3 g2(CC / GBN, BB * TT / GBM);
    sgemm_k<<<g2, 256>>>(ob_p, Wo, out, BB * TT, CC, CC);
}

// round 3
// speedup vs baseline: 2.0652x; 2.0652x over previous
#include <cuda_runtime.h>
#include <cuda_bf16.h>
#include <cstdint>
#include <cstddef>

#define BB 4
#define TT 4096
#define CC 1024
#define HH 16
#define GG 8
#define HSD 64
#define GTT 512

// ---- scratch (static device globals; no runtime allocation allowed) ----
__device__ __align__(16) float g_qkv[(size_t)BB*TT*3*CC];        // 192 MB
__device__ __align__(16) float g_qa[(size_t)BB*HH*GG*GTT*HSD];   // 64 MB
__device__ __align__(16) float g_ka[(size_t)BB*HH*GG*GTT*HSD];
__device__ __align__(16) float g_va[(size_t)BB*HH*GG*GTT*HSD];
// split-bf16 operands
__device__ __align__(16) __nv_bfloat16 g_xh[(size_t)BB*TT*CC];
__device__ __align__(16) __nv_bfloat16 g_xl[(size_t)BB*TT*CC];
__device__ __align__(16) __nv_bfloat16 g_wqh[(size_t)CC*3*CC];
__device__ __align__(16) __nv_bfloat16 g_wql[(size_t)CC*3*CC];
__device__ __align__(16) __nv_bfloat16 g_woh[(size_t)CC*CC];
__device__ __align__(16) __nv_bfloat16 g_wol[(size_t)CC*CC];
__device__ __align__(16) __nv_bfloat16 g_obh[(size_t)BB*TT*CC];
__device__ __align__(16) __nv_bfloat16 g_obl[(size_t)BB*TT*CC];

// =================== fp32 -> split bf16 (hi + lo) ===================
__global__ __launch_bounds__(256) void split_k(
    const float* __restrict__ in, __nv_bfloat16* __restrict__ hi,
    __nv_bfloat16* __restrict__ lo, int n)
{
    int i = (blockIdx.x * 256 + threadIdx.x) * 4;
    if (i >= n) return;
    float4 v = *(const float4*)(in + i);
    __nv_bfloat16 h0 = __float2bfloat16(v.x);
    __nv_bfloat16 h1 = __float2bfloat16(v.y);
    __nv_bfloat16 h2 = __float2bfloat16(v.z);
    __nv_bfloat16 h3 = __float2bfloat16(v.w);
    __nv_bfloat16 l0 = __float2bfloat16(v.x - __bfloat162float(h0));
    __nv_bfloat16 l1 = __float2bfloat16(v.y - __bfloat162float(h1));
    __nv_bfloat16 l2 = __float2bfloat16(v.z - __bfloat162float(h2));
    __nv_bfloat16 l3 = __float2bfloat16(v.w - __bfloat162float(h3));
    __nv_bfloat162 p;
    p.x = h0; p.y = h1; *(__nv_bfloat162*)(hi + i) = p;
    p.x = h2; p.y = h3; *(__nv_bfloat162*)(hi + i + 2) = p;
    p.x = l0; p.y = l1; *(__nv_bfloat162*)(lo + i) = p;
    p.x = l2; p.y = l3; *(__nv_bfloat162*)(lo + i + 2) = p;
}

// =================== split-bf16 3-pass tensor-core GEMM ===================
// C[M,N] = A[M,K] * B[K,N], A/B given as (hi,lo) bf16 pairs, fp32 result.
// Block 128x128, K-step 32, 8 warps (2x4), warp tile 64x32, double-buffered cp.async.

#define SA_PITCH 40    // A smem row pitch (elems): 80B, conflict-free ldmatrix
#define SB_PITCH 136   // B smem row pitch (elems): 272B, conflict-free ldmatrix
#define AH_OFF 0
#define AL_OFF 5120
#define BH_OFF 10240
#define BL_OFF 14592
#define STG_ELEMS 18944
#define GEMM_SMEM (2 * STG_ELEMS * 2)   // bytes

__device__ __forceinline__ void cp16(void* s, const void* g) {
    uint32_t sa = (uint32_t)__cvta_generic_to_shared(s);
    asm volatile("cp.async.cg.shared.global [%0], [%1], 16;" :: "r"(sa), "l"(g));
}

__device__ __forceinline__ void ldsm4(uint32_t* r, uint32_t a) {
    asm volatile("ldmatrix.sync.aligned.m8n8.x4.shared.b16 {%0,%1,%2,%3},[%4];"
        : "=r"(r[0]), "=r"(r[1]), "=r"(r[2]), "=r"(r[3]) : "r"(a));
}

__device__ __forceinline__ void ldsm4t(uint32_t* r0, uint32_t* r1, uint32_t a) {
    asm volatile("ldmatrix.sync.aligned.m8n8.x4.trans.shared.b16 {%0,%1,%2,%3},[%4];"
        : "=r"(r0[0]), "=r"(r0[1]), "=r"(r1[0]), "=r"(r1[1]) : "r"(a));
}

__device__ __forceinline__ void mma_bf16(float* d, const uint32_t* a,
                                         const uint32_t* b) {
    asm volatile("mma.sync.aligned.m16n8k16.row.col.f32.bf16.bf16.f32 "
        "{%0,%1,%2,%3},{%4,%5,%6,%7},{%8,%9},{%0,%1,%2,%3};"
        : "+f"(d[0]), "+f"(d[1]), "+f"(d[2]), "+f"(d[3])
        : "r"(a[0]), "r"(a[1]), "r"(a[2]), "r"(a[3]), "r"(b[0]), "r"(b[1]));
}

__device__ __forceinline__ void prefetch_tiles(
    __nv_bfloat16* smbuf,
    const __nv_bfloat16* Ah, const __nv_bfloat16* Al,
    const __nv_bfloat16* Bh, const __nv_bfloat16* Bl,
    int bm, int bn, int N, int K, int k0, int buf, int tid)
{
    __nv_bfloat16* sb = smbuf + buf * STG_ELEMS;
    #pragma unroll
    for (int c = 0; c < 2; c++) {
        int idx = tid * 8 + c * 2048;
        int ar = idx >> 5, ak = idx & 31;
        cp16(sb + AH_OFF + ar * SA_PITCH + ak,
             Ah + (size_t)(bm + ar) * K + k0 + ak);
        cp16(sb + AL_OFF + ar * SA_PITCH + ak,
             Al + (size_t)(bm + ar) * K + k0 + ak);
        int bk = idx >> 7, bc = idx & 127;
        cp16(sb + BH_OFF + bk * SB_PITCH + bc,
             Bh + (size_t)(k0 + bk) * N + bn + bc);
        cp16(sb + BL_OFF + bk * SB_PITCH + bc,
             Bl + (size_t)(k0 + bk) * N + bn + bc);
    }
    asm volatile("cp.async.commit_group;" ::: "memory");
}

__global__ __launch_bounds__(256) void gemm3_k(
    const __nv_bfloat16* __restrict__ Ah, const __nv_bfloat16* __restrict__ Al,
    const __nv_bfloat16* __restrict__ Bh, const __nv_bfloat16* __restrict__ Bl,
    float* __restrict__ C, int M, int N, int K)
{
    extern __shared__ __nv_bfloat16 smbuf[];
    int tid = threadIdx.x, lane = tid & 31, warp = tid >> 5;
    int bm = blockIdx.y * 128, bn = blockIdx.x * 128;
    int wm = (warp >> 2) * 64, wn = (warp & 3) * 32;
    uint32_t smb = (uint32_t)__cvta_generic_to_shared(smbuf);
    float acc[4][4][4] = {};
    int NK = K >> 5;

    prefetch_tiles(smbuf, Ah, Al, Bh, Bl, bm, bn, N, K, 0, 0, tid);
    for (int kt = 0; kt < NK; kt++) {
        if (kt + 1 < NK) {
            prefetch_tiles(smbuf, Ah, Al, Bh, Bl, bm, bn, N, K,
                           (kt + 1) << 5, (kt + 1) & 1, tid);
            asm volatile("cp.async.wait_group 1;" ::: "memory");
        } else {
            asm volatile("cp.async.wait_group 0;" ::: "memory");
        }
        __syncthreads();
        int sb = (kt & 1) * STG_ELEMS;
        #pragma unroll
        for (int ks = 0; ks < 2; ks++) {
            uint32_t aH[4][4], aL[4][4], bH[4][2], bL[4][2];
            int arow = lane & 15;
            int acb = ks * 32 + ((lane >> 4) << 4);  // k16 byte offset in A row
            #pragma unroll
            for (int mt = 0; mt < 4; mt++) {
                uint32_t ad = smb + (uint32_t)((sb + AH_OFF) * 2
                            + (wm + mt * 16 + arow) * (SA_PITCH * 2) + acb);
                ldsm4(aH[mt], ad);
                ldsm4(aL[mt], ad + (AL_OFF - AH_OFF) * 2);
            }
            int bk = ks * 16 + (lane & 15);
            int bcb = (wn + ((lane >> 4) << 3)) * 2;
            #pragma unroll
            for (int p = 0; p < 2; p++) {
                uint32_t bd = smb + (uint32_t)((sb + BH_OFF) * 2
                            + bk * (SB_PITCH * 2) + bcb + p * 32);
                ldsm4t(bH[2 * p], bH[2 * p + 1], bd);
                ldsm4t(bL[2 * p], bL[2 * p + 1], bd + (BL_OFF - BH_OFF) * 2);
            }
            #pragma unroll
            for (int mt = 0; mt < 4; mt++)
                #pragma unroll
                for (int nt = 0; nt < 4; nt++) {
                    mma_bf16(acc[mt][nt], aH[mt], bH[nt]);
                    mma_bf16(acc[mt][nt], aH[mt], bL[nt]);
                    mma_bf16(acc[mt][nt], aL[mt], bH[nt]);
                }
        }
        __syncthreads();
    }
    #pragma unroll
    for (int mt = 0; mt < 4; mt++) {
        #pragma unroll
        for (int nt = 0; nt < 4; nt++) {
            int r = bm + wm + mt * 16 + (lane >> 2);
            int c = bn + wn + nt * 8 + ((lane & 3) << 1);
            *(float2*)&C[(size_t)r * N + c] =
                make_float2(acc[mt][nt][0], acc[mt][nt][1]);
            *(float2*)&C[(size_t)(r + 8) * N + c] =
                make_float2(acc[mt][nt][2], acc[mt][nt][3]);
        }
    }
}

// =================== RoPE + grouped scatter ===================
__global__ __launch_bounds__(256) void rope_k(
    const float* __restrict__ fcos, const float* __restrict__ fsin)
{
    unsigned id = blockIdx.x * 256u + threadIdx.x;
    int j = id & 31;
    int t = (id >> 5) & (TT - 1);
    int h = (id >> 17) & (HH - 1);
    int b = id >> 21;
    const float* row = g_qkv + (size_t)(b * TT + t) * (3 * CC);
    float2 qv = *(const float2*)(row + h * HSD + 2 * j);
    float2 kv = *(const float2*)(row + CC + h * HSD + 2 * j);
    float2 vv = *(const float2*)(row + 2 * CC + h * HSD + 2 * j);
    float c = fcos[t * 32 + j];
    float s = fsin[t * 32 + j];
    float2 qo = make_float2(qv.x * c - qv.y * s, qv.x * s + qv.y * c);
    float2 ko = make_float2(kv.x * c - kv.y * s, kv.x * s + kv.y * c);
    int h2 = t & 15;
    int gq = h >> 1;
    int gtq = ((h & 1) << 8) | (t >> 4);
    size_t qidx = (((size_t)((b * HH + h2) * GG + gq) * GTT + gtq) * HSD) + 2 * j;
    *(float2*)(g_qa + qidx) = qo;
    *(float2*)(g_ka + qidx) = ko;
    int gv = t >> 9, gtv = t & 511;
    size_t vidx = (((size_t)((b * HH + h) * GG + gv) * GTT + gtv) * HSD) + 2 * j;
    *(float2*)(g_va + vidx) = vv;
}

// =================== Block-local causal flash attention ===================
#define PADA 68
#define ATT_SMEM ((4 * 64 * PADA + 3 * 64) * sizeof(float))

__global__ __launch_bounds__(256) void attn_k() {
    extern __shared__ float sm[];
    float* Qs = sm;
    float* Ks = sm + 64 * PADA;
    float* Vs = sm + 2 * 64 * PADA;
    float* Pb = sm + 3 * 64 * PADA;
    float* mrow = sm + 4 * 64 * PADA;
    float* lrow = mrow + 64;
    float* crow = mrow + 128;

    int bx = blockIdx.x;
    int qt = bx & 7;
    int g  = (bx >> 3) & 7;
    int h  = (bx >> 6) & 15;
    int b  = bx >> 10;
    size_t base = ((size_t)((b * HH + h) * GG + g)) * GTT * HSD;
    const float* Qb = g_qa + base;
    const float* Kb = g_ka + base;
    const float* Vb = g_va + base;

    int tid = threadIdx.x;
    int tr = tid >> 4, tc = tid & 15;
    int lq  = tid & 15;
    int ld4 = (tid >> 4) << 2;

    #pragma unroll
    for (int it = 0; it < 4; it++) {
        int q = lq + it * 16;
        float4 v = *(const float4*)(Qb + (size_t)(qt * 64 + q) * HSD + ld4);
        Qs[(ld4 + 0) * PADA + q] = v.x * 0.125f;
        Qs[(ld4 + 1) * PADA + q] = v.y * 0.125f;
        Qs[(ld4 + 2) * PADA + q] = v.z * 0.125f;
        Qs[(ld4 + 3) * PADA + q] = v.w * 0.125f;
    }
    if (tid < 64) { mrow[tid] = -3.0e38f; lrow[tid] = 0.f; crow[tid] = 0.f; }

    float oacc[4][4] = {};

    for (int kt = 0; kt <= qt; kt++) {
        __syncthreads();
        #pragma unroll
        for (int it = 0; it < 4; it++) {
            int jj = lq + it * 16;
            float4 kv = *(const float4*)(Kb + (size_t)(kt * 64 + jj) * HSD + ld4);
            Ks[(ld4 + 0) * PADA + jj] = kv.x;
            Ks[(ld4 + 1) * PADA + jj] = kv.y;
            Ks[(ld4 + 2) * PADA + jj] = kv.z;
            Ks[(ld4 + 3) * PADA + jj] = kv.w;
            float4 vv = *(const float4*)(Vb + (size_t)(kt * 64 + jj) * HSD + ld4);
            *(float4*)(Vs + jj * PADA + ld4) = vv;
        }
        __syncthreads();
        float sacc[4][4] = {};
        #pragma unroll
        for (int kk = 0; kk < 64; kk++) {
            float4 a  = *(float4*)(Qs + kk * PADA + tr * 4);
            float4 bv = *(float4*)(Ks + kk * PADA + tc * 4);
            float ar[4] = {a.x, a.y, a.z, a.w};
            float br[4] = {bv.x, bv.y, bv.z, bv.w};
            #pragma unroll
            for (int i = 0; i < 4; i++)
                #pragma unroll
                for (int j = 0; j < 4; j++)
                    sacc[i][j] = fmaf(ar[i], br[j], sacc[i][j]);
        }
        bool diag = (kt == qt);
        #pragma unroll
        for (int i = 0; i < 4; i++)
            #pragma unroll
            for (int j = 0; j < 4; j++) {
                float sv = sacc[i][j];
                if (diag && (tc * 4 + j) > (tr * 4 + i)) sv = -1e30f;
                Pb[(tc * 4 + j) * PADA + tr * 4 + i] = sv;
            }
        __syncthreads();
        {
            int warp = tid >> 5, lane = tid & 31;
            #pragma unroll
            for (int r = 0; r < 8; r++) {
                int q = warp * 8 + r;
                float s1 = Pb[lane * PADA + q];
                float s2 = Pb[(lane + 32) * PADA + q];
                float mx = fmaxf(s1, s2);
                #pragma unroll
                for (int off = 16; off > 0; off >>= 1)
                    mx = fmaxf(mx, __shfl_xor_sync(0xffffffffu, mx, off));
                float mold = mrow[q];
                float mnew = fmaxf(mold, mx);
                float p1 = __expf(s1 - mnew);
                float p2 = __expf(s2 - mnew);
                float ps = p1 + p2;
                #pragma unroll
                for (int off = 16; off > 0; off >>= 1)
                    ps += __shfl_xor_sync(0xffffffffu, ps, off);
                if (lane == 0) {
                    float corr = __expf(mold - mnew);
                    crow[q] = corr;
                    lrow[q] = lrow[q] * corr + ps;
                    mrow[q] = mnew;
                }
                Pb[lane * PADA + q] = p1;
                Pb[(lane + 32) * PADA + q] = p2;
            }
        }
        __syncthreads();
        float cr[4];
        #pragma unroll
        for (int i = 0; i < 4; i++) cr[i] = crow[tr * 4 + i];
        #pragma unroll
        for (int i = 0; i < 4; i++)
            #pragma unroll
            for (int j = 0; j < 4; j++) oacc[i][j] *= cr[i];
        #pragma unroll
        for (int kk = 0; kk < 64; kk++) {
            float4 a  = *(float4*)(Pb + kk * PADA + tr * 4);
            float4 bv = *(float4*)(Vs + kk * PADA + tc * 4);
            float ar[4] = {a.x, a.y, a.z, a.w};
            float br[4] = {bv.x, bv.y, bv.z, bv.w};
            #pragma unroll
            for (int i = 0; i < 4; i++)
                #pragma unroll
                for (int j = 0; j < 4; j++)
                    oacc[i][j] = fmaf(ar[i], br[j], oacc[i][j]);
        }
    }
    __syncthreads();
    // epilogue: normalize, un-group, emit split-bf16 directly for GEMM2
    size_t rowbase = (size_t)b * TT + g * GTT + qt * 64;
    int colb = h * HSD + tc * 4;
    #pragma unroll
    for (int i = 0; i < 4; i++) {
        float linv = 1.0f / lrow[tr * 4 + i];
        size_t off = (rowbase + tr * 4 + i) * CC + colb;
        float v0 = oacc[i][0] * linv, v1 = oacc[i][1] * linv;
        float v2 = oacc[i][2] * linv, v3 = oacc[i][3] * linv;
        __nv_bfloat16 h0 = __float2bfloat16(v0), h1 = __float2bfloat16(v1);
        __nv_bfloat16 h2 = __float2bfloat16(v2), h3 = __float2bfloat16(v3);
        __nv_bfloat162 p;
        p.x = h0; p.y = h1; *(__nv_bfloat162*)(g_obh + off) = p;
        p.x = h2; p.y = h3; *(__nv_bfloat162*)(g_obh + off + 2) = p;
        p.x = __float2bfloat16(v0 - __bfloat162float(h0));
        p.y = __float2bfloat16(v1 - __bfloat162float(h1));
        *(__nv_bfloat162*)(g_obl + off) = p;
        p.x = __float2bfloat16(v2 - __bfloat162float(h2));
        p.y = __float2bfloat16(v3 - __bfloat162float(h3));
        *(__nv_bfloat162*)(g_obl + off + 2) = p;
    }
}

// =================== Pooling (qb/kb/vb; L=1 attention is identity) ===================
__global__ __launch_bounds__(64) void pool_k(
    const float* __restrict__ qp, const float* __restrict__ kp,
    const float* __restrict__ vp, float* __restrict__ out)
{
    int bx = blockIdx.x;
    int which = bx / 448;
    int rem = bx - which * 448;
    int g = rem % 7;
    int bh = rem / 7;
    const float* src = (which == 0 ? g_qa : (which == 1 ? g_ka : g_va))
                     + ((size_t)bh * GG + g) * GTT * HSD;
    const float* proj = (which == 0 ? qp : (which == 1 ? kp : vp));
    int hs = threadIdx.x;
    float acc = 0.f;
    #pragma unroll 8
    for (int t = 0; t < GTT; t++)
        acc = fmaf(src[(size_t)t * HSD + hs], proj[t], acc);
    out[(size_t)BB * TT * CC + (size_t)which * (BB * HH * 7 * HSD)
        + (size_t)(bh * 7 + g) * HSD + hs] = acc;
}

// =================== launch ===================
extern "C" void kernel_launch(void* const* d_in, const int* in_sizes, int n_in,
                              void* d_out, int out_size) {
    (void)in_sizes; (void)n_in; (void)out_size;
    const float* x    = (const float*)d_in[0];
    const float* Wqkv = (const float*)d_in[1];
    const float* Wo   = (const float*)d_in[2];
    const float* qp   = (const float*)d_in[3];
    const float* kp   = (const float*)d_in[4];
    const float* vp   = (const float*)d_in[5];
    const float* fc   = (const float*)d_in[6];
    const float* fs   = (const float*)d_in[7];
    float* out = (float*)d_out;

    float *qkv_p;
    __nv_bfloat16 *xh, *xl, *wqh, *wql, *woh, *wol, *obh, *obl;
    cudaGetSymbolAddress((void**)&qkv_p, g_qkv);
    cudaGetSymbolAddress((void**)&xh, g_xh);
    cudaGetSymbolAddress((void**)&xl, g_xl);
    cudaGetSymbolAddress((void**)&wqh, g_wqh);
    cudaGetSymbolAddress((void**)&wql, g_wql);
    cudaGetSymbolAddress((void**)&woh, g_woh);
    cudaGetSymbolAddress((void**)&wol, g_wol);
    cudaGetSymbolAddress((void**)&obh, g_obh);
    cudaGetSymbolAddress((void**)&obl, g_obl);

    cudaFuncSetAttribute(attn_k, cudaFuncAttributeMaxDynamicSharedMemorySize,
                         (int)ATT_SMEM);
    cudaFuncSetAttribute(gemm3_k, cudaFuncAttributeMaxDynamicSharedMemorySize,
                         GEMM_SMEM);

    // 0) split inputs to bf16 hi/lo
    int nx = BB * TT * CC;
    split_k<<<(nx / 4 + 255) / 256, 256>>>(x, xh, xl, nx);
    int nwq = CC * 3 * CC;
    split_k<<<(nwq / 4 + 255) / 256, 256>>>(Wqkv, wqh, wql, nwq);
    int nwo = CC * CC;
    split_k<<<(nwo / 4 + 255) / 256, 256>>>(Wo, woh, wol, nwo);

    // 1) qkv = x @ Wqkv  (tensor cores, 3-pass split bf16)
    dim3 g1(3 * CC / 128, BB * TT / 128);
    gemm3_k<<<g1, 256, GEMM_SMEM>>>(xh, xl, wqh, wql, qkv_p,
                                    BB * TT, 3 * CC, CC);
    // 2) rope + grouped scatter
    rope_k<<<(BB * HH * TT * 32) / 256, 256>>>(fc, fs);
    // 3) block-local causal attention (emits split-bf16 o)
    attn_k<<<BB * HH * GG * 8, 256, ATT_SMEM>>>();
    // 4) qb/kb/vb pools (writes tail of d_out)
    pool_k<<<3 * BB * HH * 7, 64>>>(qp, kp, vp, out);
    // 5) out = o @ Wo (writes head of d_out)
    dim3 g2(CC / 128, BB * TT / 128);
    gemm3_k<<<g2, 256, GEMM_SMEM>>>(obh, obl, woh, wol, out,
                                    BB * TT, CC, CC);
}

// round 4
// speedup vs baseline: 2.7881x; 1.3501x over previous
#include <cuda_runtime.h>
#include <cuda_bf16.h>
#include <cstdint>
#include <cstddef>

#define BB 4
#define TT 4096
#define CC 1024
#define HH 16
#define GG 8
#define HSD 64
#define GTT 512

// ---- scratch (static device globals; no runtime allocation allowed) ----
__device__ __align__(16) float g_qkv[(size_t)BB*TT*3*CC];        // 192 MB
// grouped, rope'd, split-bf16 q/k/v
__device__ __align__(16) __nv_bfloat16 g_qh[(size_t)BB*HH*GG*GTT*HSD];
__device__ __align__(16) __nv_bfloat16 g_ql[(size_t)BB*HH*GG*GTT*HSD];
__device__ __align__(16) __nv_bfloat16 g_kh[(size_t)BB*HH*GG*GTT*HSD];
__device__ __align__(16) __nv_bfloat16 g_kl[(size_t)BB*HH*GG*GTT*HSD];
__device__ __align__(16) __nv_bfloat16 g_vh[(size_t)BB*HH*GG*GTT*HSD];
__device__ __align__(16) __nv_bfloat16 g_vl[(size_t)BB*HH*GG*GTT*HSD];
// split-bf16 GEMM operands
__device__ __align__(16) __nv_bfloat16 g_xh[(size_t)BB*TT*CC];
__device__ __align__(16) __nv_bfloat16 g_xl[(size_t)BB*TT*CC];
__device__ __align__(16) __nv_bfloat16 g_wqh[(size_t)CC*3*CC];
__device__ __align__(16) __nv_bfloat16 g_wql[(size_t)CC*3*CC];
__device__ __align__(16) __nv_bfloat16 g_woh[(size_t)CC*CC];
__device__ __align__(16) __nv_bfloat16 g_wol[(size_t)CC*CC];
__device__ __align__(16) __nv_bfloat16 g_obh[(size_t)BB*TT*CC];
__device__ __align__(16) __nv_bfloat16 g_obl[(size_t)BB*TT*CC];

// =================== small helpers ===================
__device__ __forceinline__ float hif(float x) {
    return __bfloat162float(__float2bfloat16(x));
}
__device__ __forceinline__ uint32_t packbf(float lo, float hi) {
    uint32_t r;
    asm("cvt.rn.bf16x2.f32 %0,%1,%2;" : "=r"(r) : "f"(hi), "f"(lo));
    return r;
}
__device__ __forceinline__ void cp16(void* s, const void* g) {
    uint32_t sa = (uint32_t)__cvta_generic_to_shared(s);
    asm volatile("cp.async.cg.shared.global [%0], [%1], 16;" :: "r"(sa), "l"(g));
}
__device__ __forceinline__ void cp16s(uint32_t sa, const void* g) {
    asm volatile("cp.async.cg.shared.global [%0], [%1], 16;" :: "r"(sa), "l"(g));
}
__device__ __forceinline__ void ldsm4(uint32_t* r, uint32_t a) {
    asm volatile("ldmatrix.sync.aligned.m8n8.x4.shared.b16 {%0,%1,%2,%3},[%4];"
        : "=r"(r[0]), "=r"(r[1]), "=r"(r[2]), "=r"(r[3]) : "r"(a));
}
__device__ __forceinline__ void ldsm4t(uint32_t* r0, uint32_t* r1, uint32_t a) {
    asm volatile("ldmatrix.sync.aligned.m8n8.x4.trans.shared.b16 {%0,%1,%2,%3},[%4];"
        : "=r"(r0[0]), "=r"(r0[1]), "=r"(r1[0]), "=r"(r1[1]) : "r"(a));
}
__device__ __forceinline__ void ldsm4t4(uint32_t* r, uint32_t a) {
    asm volatile("ldmatrix.sync.aligned.m8n8.x4.trans.shared.b16 {%0,%1,%2,%3},[%4];"
        : "=r"(r[0]), "=r"(r[1]), "=r"(r[2]), "=r"(r[3]) : "r"(a));
}
__device__ __forceinline__ void mma_bf16(float* d, const uint32_t* a,
                                         const uint32_t* b) {
    asm volatile("mma.sync.aligned.m16n8k16.row.col.f32.bf16.bf16.f32 "
        "{%0,%1,%2,%3},{%4,%5,%6,%7},{%8,%9},{%0,%1,%2,%3};"
        : "+f"(d[0]), "+f"(d[1]), "+f"(d[2]), "+f"(d[3])
        : "r"(a[0]), "r"(a[1]), "r"(a[2]), "r"(a[3]), "r"(b[0]), "r"(b[1]));
}

// =================== fp32 -> split bf16 (hi + lo) ===================
__global__ __launch_bounds__(256) void split_k(
    const float* __restrict__ in, __nv_bfloat16* __restrict__ hi,
    __nv_bfloat16* __restrict__ lo, int n)
{
    int i = (blockIdx.x * 256 + threadIdx.x) * 4;
    if (i >= n) return;
    float4 v = *(const float4*)(in + i);
    float h0 = hif(v.x), h1 = hif(v.y), h2 = hif(v.z), h3 = hif(v.w);
    *(uint32_t*)(hi + i)     = packbf(h0, h1);
    *(uint32_t*)(hi + i + 2) = packbf(h2, h3);
    *(uint32_t*)(lo + i)     = packbf(v.x - h0, v.y - h1);
    *(uint32_t*)(lo + i + 2) = packbf(v.z - h2, v.w - h3);
}

// =================== split-bf16 3-pass tensor-core GEMM ===================
#define SA_PITCH 40
#define SB_PITCH 136
#define AH_OFF 0
#define AL_OFF 5120
#define BH_OFF 10240
#define BL_OFF 14592
#define STG_ELEMS 18944
#define GEMM_SMEM (2 * STG_ELEMS * 2)

__device__ __forceinline__ void prefetch_tiles(
    __nv_bfloat16* smbuf,
    const __nv_bfloat16* Ah, const __nv_bfloat16* Al,
    const __nv_bfloat16* Bh, const __nv_bfloat16* Bl,
    int bm, int bn, int N, int K, int k0, int buf, int tid)
{
    __nv_bfloat16* sb = smbuf + buf * STG_ELEMS;
    #pragma unroll
    for (int c = 0; c < 2; c++) {
        int idx = tid * 8 + c * 2048;
        int ar = idx >> 5, ak = idx & 31;
        cp16(sb + AH_OFF + ar * SA_PITCH + ak,
             Ah + (size_t)(bm + ar) * K + k0 + ak);
        cp16(sb + AL_OFF + ar * SA_PITCH + ak,
             Al + (size_t)(bm + ar) * K + k0 + ak);
        int bk = idx >> 7, bc = idx & 127;
        cp16(sb + BH_OFF + bk * SB_PITCH + bc,
             Bh + (size_t)(k0 + bk) * N + bn + bc);
        cp16(sb + BL_OFF + bk * SB_PITCH + bc,
             Bl + (size_t)(k0 + bk) * N + bn + bc);
    }
    asm volatile("cp.async.commit_group;" ::: "memory");
}

__global__ __launch_bounds__(256) void gemm3_k(
    const __nv_bfloat16* __restrict__ Ah, const __nv_bfloat16* __restrict__ Al,
    const __nv_bfloat16* __restrict__ Bh, const __nv_bfloat16* __restrict__ Bl,
    float* __restrict__ C, int M, int N, int K)
{
    extern __shared__ __nv_bfloat16 smbuf[];
    int tid = threadIdx.x, lane = tid & 31, warp = tid >> 5;
    int bm = blockIdx.y * 128, bn = blockIdx.x * 128;
    int wm = (warp >> 2) * 64, wn = (warp & 3) * 32;
    uint32_t smb = (uint32_t)__cvta_generic_to_shared(smbuf);
    float acc[4][4][4] = {};
    int NK = K >> 5;

    prefetch_tiles(smbuf, Ah, Al, Bh, Bl, bm, bn, N, K, 0, 0, tid);
    for (int kt = 0; kt < NK; kt++) {
        if (kt + 1 < NK) {
            prefetch_tiles(smbuf, Ah, Al, Bh, Bl, bm, bn, N, K,
                           (kt + 1) << 5, (kt + 1) & 1, tid);
            asm volatile("cp.async.wait_group 1;" ::: "memory");
        } else {
            asm volatile("cp.async.wait_group 0;" ::: "memory");
        }
        __syncthreads();
        int sb = (kt & 1) * STG_ELEMS;
        #pragma unroll
        for (int ks = 0; ks < 2; ks++) {
            uint32_t aH[4][4], aL[4][4], bH[4][2], bL[4][2];
            int arow = lane & 15;
            int acb = ks * 32 + ((lane >> 4) << 4);
            #pragma unroll
            for (int mt = 0; mt < 4; mt++) {
                uint32_t ad = smb + (uint32_t)((sb + AH_OFF) * 2
                            + (wm + mt * 16 + arow) * (SA_PITCH * 2) + acb);
                ldsm4(aH[mt], ad);
                ldsm4(aL[mt], ad + (AL_OFF - AH_OFF) * 2);
            }
            int bk = ks * 16 + (lane & 15);
            int bcb = (wn + ((lane >> 4) << 3)) * 2;
            #pragma unroll
            for (int p = 0; p < 2; p++) {
                uint32_t bd = smb + (uint32_t)((sb + BH_OFF) * 2
                            + bk * (SB_PITCH * 2) + bcb + p * 32);
                ldsm4t(bH[2 * p], bH[2 * p + 1], bd);
                ldsm4t(bL[2 * p], bL[2 * p + 1], bd + (BL_OFF - BH_OFF) * 2);
            }
            #pragma unroll
            for (int mt = 0; mt < 4; mt++)
                #pragma unroll
                for (int nt = 0; nt < 4; nt++) {
                    mma_bf16(acc[mt][nt], aH[mt], bH[nt]);
                    mma_bf16(acc[mt][nt], aH[mt], bL[nt]);
                    mma_bf16(acc[mt][nt], aL[mt], bH[nt]);
                }
        }
        __syncthreads();
    }
    #pragma unroll
    for (int mt = 0; mt < 4; mt++) {
        #pragma unroll
        for (int nt = 0; nt < 4; nt++) {
            int r = bm + wm + mt * 16 + (lane >> 2);
            int c = bn + wn + nt * 8 + ((lane & 3) << 1);
            *(float2*)&C[(size_t)r * N + c] =
                make_float2(acc[mt][nt][0], acc[mt][nt][1]);
            *(float2*)&C[(size_t)(r + 8) * N + c] =
                make_float2(acc[mt][nt][2], acc[mt][nt][3]);
        }
    }
}

// =================== RoPE + grouped scatter (emit split bf16) ===================
__device__ __forceinline__ void store_split2(
    __nv_bfloat16* hi, __nv_bfloat16* lo, size_t idx, float2 v)
{
    float h0 = hif(v.x), h1 = hif(v.y);
    *(uint32_t*)(hi + idx) = packbf(h0, h1);
    *(uint32_t*)(lo + idx) = packbf(v.x - h0, v.y - h1);
}

__global__ __launch_bounds__(256) void rope_k(
    const float* __restrict__ fcos, const float* __restrict__ fsin)
{
    unsigned id = blockIdx.x * 256u + threadIdx.x;
    int j = id & 31;
    int t = (id >> 5) & (TT - 1);
    int h = (id >> 17) & (HH - 1);
    int b = id >> 21;
    const float* row = g_qkv + (size_t)(b * TT + t) * (3 * CC);
    float2 qv = *(const float2*)(row + h * HSD + 2 * j);
    float2 kv = *(const float2*)(row + CC + h * HSD + 2 * j);
    float2 vv = *(const float2*)(row + 2 * CC + h * HSD + 2 * j);
    float c = fcos[t * 32 + j];
    float s = fsin[t * 32 + j];
    float2 qo = make_float2(qv.x * c - qv.y * s, qv.x * s + qv.y * c);
    float2 ko = make_float2(kv.x * c - kv.y * s, kv.x * s + kv.y * c);
    // q/k grouped view scramble: h2 = t&15, g = h>>1, gt = (h&1)*256 + (t>>4)
    int h2 = t & 15;
    int gq = h >> 1;
    int gtq = ((h & 1) << 8) | (t >> 4);
    size_t qidx = (((size_t)((b * HH + h2) * GG + gq) * GTT + gtq) * HSD) + 2 * j;
    store_split2(g_qh, g_ql, qidx, qo);
    store_split2(g_kh, g_kl, qidx, ko);
    // v natural grouping
    int gv = t >> 9, gtv = t & 511;
    size_t vidx = (((size_t)((b * HH + h) * GG + gv) * GTT + gtv) * HSD) + 2 * j;
    store_split2(g_vh, g_vl, vidx, vv);
}

// =================== tensor-core block-causal flash attention ===================
// CTA: 128 q-rows of one (b,h,g); 8 warps x 16 rows; split-bf16 3-pass QK & PV.
// smem: 2 buffers x {Kh,Kl,Vh,Vl} each 64x64 bf16 (8KB) = 64KB. XOR-swizzled.
#define ATT_SMEM 65536

__device__ __forceinline__ uint32_t swz(int r, int c) {
    return (uint32_t)(r * 128 + ((c ^ (r & 7)) << 4));
}

__global__ __launch_bounds__(256) void attn_k() {
    extern __shared__ __align__(16) char smraw[];
    uint32_t smb = (uint32_t)__cvta_generic_to_shared(smraw);
    int tid = threadIdx.x, lane = tid & 31, w = tid >> 5;
    int bx = blockIdx.x;
    int qi = bx & 3;
    int g  = (bx >> 2) & 7;
    int h  = (bx >> 5) & 15;
    int b  = bx >> 9;
    size_t gb = ((size_t)((b * HH + h) * GG + g)) * GTT * HSD;
    const __nv_bfloat16* Qhp = g_qh + gb + (size_t)(128 * qi) * HSD;
    const __nv_bfloat16* Qlp = g_ql + gb + (size_t)(128 * qi) * HSD;
    const __nv_bfloat16* arrp[4] = { g_kh + gb, g_kl + gb, g_vh + gb, g_vl + gb };

    // ---- stage Q (128x64 hi/lo) into buffer1 region (offset 32768) ----
    #pragma unroll
    for (int it = 0; it < 8; it++) {
        int cid = tid + it * 256;
        int half = cid >> 10;
        int rc = cid & 1023;
        int r = rc >> 3, c = rc & 7;
        const __nv_bfloat16* src = (half ? Qlp : Qhp) + r * HSD + c * 8;
        cp16s(smb + 32768 + half * 16384 + swz(r, c), src);
    }
    asm volatile("cp.async.commit_group;" ::: "memory");
    asm volatile("cp.async.wait_group 0;" ::: "memory");
    __syncthreads();

    // ---- load Q fragments (warp rows w*16..w*16+15) ----
    uint32_t qhf[4][4], qlf[4][4];
    int rq = w * 16;
    int sub = lane >> 3;
    #pragma unroll
    for (int kk = 0; kk < 4; kk++) {
        int r = rq + (sub & 1) * 8 + (lane & 7);
        int c = 2 * kk + (sub >> 1);
        uint32_t ad = smb + 32768 + swz(r, c);
        ldsm4(qhf[kk], ad);
        ldsm4(qlf[kk], ad + 16384);
    }
    __syncthreads();

    int ntiles = 2 * qi + 2;

    // prefetch kt=0 into buffer 0
    {
        #pragma unroll
        for (int it = 0; it < 8; it++) {
            int cid = tid + it * 256;
            int arr = cid >> 9;
            int rc = cid & 511;
            int r = rc >> 3, c = rc & 7;
            cp16s(smb + arr * 8192 + swz(r, c),
                  arrp[arr] + (size_t)r * HSD + c * 8);
        }
        asm volatile("cp.async.commit_group;" ::: "memory");
    }

    float oacc[8][4] = {};
    float m_lo = -1e30f, m_hi = -1e30f, l_lo = 0.f, l_hi = 0.f;

    for (int kt = 0; kt < ntiles; kt++) {
        if (kt + 1 < ntiles) {
            int buf = (kt + 1) & 1;
            #pragma unroll
            for (int it = 0; it < 8; it++) {
                int cid = tid + it * 256;
                int arr = cid >> 9;
                int rc = cid & 511;
                int r = rc >> 3, c = rc & 7;
                cp16s(smb + buf * 32768 + arr * 8192 + swz(r, c),
                      arrp[arr] + (size_t)((kt + 1) * 64 + r) * HSD + c * 8);
            }
            asm volatile("cp.async.commit_group;" ::: "memory");
            asm volatile("cp.async.wait_group 1;" ::: "memory");
        } else {
            asm volatile("cp.async.wait_group 0;" ::: "memory");
        }
        __syncthreads();
        uint32_t kb0 = smb + (kt & 1) * 32768;

        // ---- S = Q K^T (3-pass split) ----
        float sacc[8][4] = {};
        #pragma unroll
        for (int kk = 0; kk < 4; kk++) {
            #pragma unroll
            for (int tp = 0; tp < 4; tp++) {
                uint32_t kh4[4], kl4[4];
                int r = tp * 16 + (sub >> 1) * 8 + (lane & 7);
                int c = 2 * kk + (sub & 1);
                uint32_t ad = kb0 + swz(r, c);
                ldsm4(kh4, ad);
                ldsm4(kl4, ad + 8192);
                mma_bf16(sacc[2 * tp],     qhf[kk], kh4);
                mma_bf16(sacc[2 * tp],     qhf[kk], kl4);
                mma_bf16(sacc[2 * tp],     qlf[kk], kh4);
                mma_bf16(sacc[2 * tp + 1], qhf[kk], kh4 + 2);
                mma_bf16(sacc[2 * tp + 1], qhf[kk], kl4 + 2);
                mma_bf16(sacc[2 * tp + 1], qlf[kk], kh4 + 2);
            }
        }

        // ---- scale + causal mask ----
        int rowl = 128 * qi + w * 16 + (lane >> 2);
        bool nm = (kt * 64 + 63) > (128 * qi + w * 16);
        #pragma unroll
        for (int t = 0; t < 8; t++) {
            #pragma unroll
            for (int e = 0; e < 4; e++) {
                float s = sacc[t][e] * 0.125f;
                if (nm) {
                    int col = kt * 64 + t * 8 + ((lane & 3) << 1) + (e & 1);
                    int row = rowl + ((e & 2) ? 8 : 0);
                    if (col > row) s = -1e30f;
                }
                sacc[t][e] = s;
            }
        }

        // ---- online softmax (rows owned by lane quads) ----
        float mlo = -1e30f, mhi = -1e30f;
        #pragma unroll
        for (int t = 0; t < 8; t++) {
            mlo = fmaxf(mlo, fmaxf(sacc[t][0], sacc[t][1]));
            mhi = fmaxf(mhi, fmaxf(sacc[t][2], sacc[t][3]));
        }
        mlo = fmaxf(mlo, __shfl_xor_sync(0xffffffffu, mlo, 1));
        mlo = fmaxf(mlo, __shfl_xor_sync(0xffffffffu, mlo, 2));
        mhi = fmaxf(mhi, __shfl_xor_sync(0xffffffffu, mhi, 1));
        mhi = fmaxf(mhi, __shfl_xor_sync(0xffffffffu, mhi, 2));
        float nmlo = fmaxf(m_lo, mlo), nmhi = fmaxf(m_hi, mhi);
        float clo = __expf(m_lo - nmlo), chi = __expf(m_hi - nmhi);
        m_lo = nmlo; m_hi = nmhi;
        float slo = 0.f, shi = 0.f;
        #pragma unroll
        for (int t = 0; t < 8; t++) {
            float p0 = __expf(sacc[t][0] - nmlo);
            float p1 = __expf(sacc[t][1] - nmlo);
            float p2 = __expf(sacc[t][2] - nmhi);
            float p3 = __expf(sacc[t][3] - nmhi);
            sacc[t][0] = p0; sacc[t][1] = p1; sacc[t][2] = p2; sacc[t][3] = p3;
            slo += p0 + p1; shi += p2 + p3;
        }
        slo += __shfl_xor_sync(0xffffffffu, slo, 1);
        slo += __shfl_xor_sync(0xffffffffu, slo, 2);
        shi += __shfl_xor_sync(0xffffffffu, shi, 1);
        shi += __shfl_xor_sync(0xffffffffu, shi, 2);
        l_lo = l_lo * clo + slo;
        l_hi = l_hi * chi + shi;
        #pragma unroll
        for (int t = 0; t < 8; t++) {
            oacc[t][0] *= clo; oacc[t][1] *= clo;
            oacc[t][2] *= chi; oacc[t][3] *= chi;
        }

        // ---- O += P V (3-pass split) ----
        #pragma unroll
        for (int jk = 0; jk < 4; jk++) {
            uint32_t aph[4], apl[4];
            {
                int t0 = 2 * jk, t1 = t0 + 1;
                float h0 = hif(sacc[t0][0]), h1 = hif(sacc[t0][1]);
                float h2 = hif(sacc[t0][2]), h3 = hif(sacc[t0][3]);
                float g0 = hif(sacc[t1][0]), g1 = hif(sacc[t1][1]);
                float g2 = hif(sacc[t1][2]), g3 = hif(sacc[t1][3]);
                aph[0] = packbf(h0, h1); aph[1] = packbf(h2, h3);
                aph[2] = packbf(g0, g1); aph[3] = packbf(g2, g3);
                apl[0] = packbf(sacc[t0][0] - h0, sacc[t0][1] - h1);
                apl[1] = packbf(sacc[t0][2] - h2, sacc[t0][3] - h3);
                apl[2] = packbf(sacc[t1][0] - g0, sacc[t1][1] - g1);
                apl[3] = packbf(sacc[t1][2] - g2, sacc[t1][3] - g3);
            }
            #pragma unroll
            for (int dp = 0; dp < 4; dp++) {
                uint32_t vh4[4], vl4[4];
                int r = jk * 16 + (sub & 1) * 8 + (lane & 7);
                int c = 2 * dp + (sub >> 1);
                uint32_t ad = kb0 + 16384 + swz(r, c);
                ldsm4t4(vh4, ad);
                ldsm4t4(vl4, ad + 8192);
                mma_bf16(oacc[2 * dp],     aph, vh4);
                mma_bf16(oacc[2 * dp],     aph, vl4);
                mma_bf16(oacc[2 * dp],     apl, vh4);
                mma_bf16(oacc[2 * dp + 1], aph, vh4 + 2);
                mma_bf16(oacc[2 * dp + 1], aph, vl4 + 2);
                mma_bf16(oacc[2 * dp + 1], apl, vh4 + 2);
            }
        }
        __syncthreads();
    }

    // ---- epilogue: normalize, un-group, emit split-bf16 ----
    float ilo = 1.0f / l_lo, ihi = 1.0f / l_hi;
    size_t tau = (size_t)b * TT + g * GTT + 128 * qi + w * 16 + (lane >> 2);
    int colb = h * HSD + ((lane & 3) << 1);
    #pragma unroll
    for (int t = 0; t < 8; t++) {
        float v0 = oacc[t][0] * ilo, v1 = oacc[t][1] * ilo;
        float v2 = oacc[t][2] * ihi, v3 = oacc[t][3] * ihi;
        float h0 = hif(v0), h1 = hif(v1), h2 = hif(v2), h3 = hif(v3);
        size_t o0 = tau * CC + colb + t * 8;
        size_t o1 = (tau + 8) * CC + colb + t * 8;
        *(uint32_t*)(g_obh + o0) = packbf(h0, h1);
        *(uint32_t*)(g_obl + o0) = packbf(v0 - h0, v1 - h1);
        *(uint32_t*)(g_obh + o1) = packbf(h2, h3);
        *(uint32_t*)(g_obl + o1) = packbf(v2 - h2, v3 - h3);
    }
}

// =================== Pooling (qb/kb/vb; L=1 attention is identity) ===================
__global__ __launch_bounds__(64) void pool_k(
    const float* __restrict__ qp, const float* __restrict__ kp,
    const float* __restrict__ vp, float* __restrict__ out)
{
    int bx = blockIdx.x;
    int which = bx / 448;
    int rem = bx - which * 448;
    int g = rem % 7;
    int bh = rem / 7;
    size_t base = ((size_t)bh * GG + g) * GTT * HSD;
    const __nv_bfloat16* sh = (which == 0 ? g_qh : (which == 1 ? g_kh : g_vh)) + base;
    const __nv_bfloat16* sl = (which == 0 ? g_ql : (which == 1 ? g_kl : g_vl)) + base;
    const float* proj = (which == 0 ? qp : (which == 1 ? kp : vp));
    int hs = threadIdx.x;
    float acc = 0.f;
    #pragma unroll 8
    for (int t = 0; t < GTT; t++) {
        float v = __bfloat162float(sh[(size_t)t * HSD + hs])
                + __bfloat162float(sl[(size_t)t * HSD + hs]);
        acc = fmaf(v, proj[t], acc);
    }
    out[(size_t)BB * TT * CC + (size_t)which * (BB * HH * 7 * HSD)
        + (size_t)(bh * 7 + g) * HSD + hs] = acc;
}

// =================== launch ===================
extern "C" void kernel_launch(void* const* d_in, const int* in_sizes, int n_in,
                              void* d_out, int out_size) {
    (void)in_sizes; (void)n_in; (void)out_size;
    const float* x    = (const float*)d_in[0];
    const float* Wqkv = (const float*)d_in[1];
    const float* Wo   = (const float*)d_in[2];
    const float* qp   = (const float*)d_in[3];
    const float* kp   = (const float*)d_in[4];
    const float* vp   = (const float*)d_in[5];
    const float* fc   = (const float*)d_in[6];
    const float* fs   = (const float*)d_in[7];
    float* out = (float*)d_out;

    float* qkv_p;
    __nv_bfloat16 *xh, *xl, *wqh, *wql, *woh, *wol, *obh, *obl;
    cudaGetSymbolAddress((void**)&qkv_p, g_qkv);
    cudaGetSymbolAddress((void**)&xh, g_xh);
    cudaGetSymbolAddress((void**)&xl, g_xl);
    cudaGetSymbolAddress((void**)&wqh, g_wqh);
    cudaGetSymbolAddress((void**)&wql, g_wql);
    cudaGetSymbolAddress((void**)&woh, g_woh);
    cudaGetSymbolAddress((void**)&wol, g_wol);
    cudaGetSymbolAddress((void**)&obh, g_obh);
    cudaGetSymbolAddress((void**)&obl, g_obl);

    cudaFuncSetAttribute(attn_k, cudaFuncAttributeMaxDynamicSharedMemorySize,
                         ATT_SMEM);
    cudaFuncSetAttribute(gemm3_k, cudaFuncAttributeMaxDynamicSharedMemorySize,
                         GEMM_SMEM);

    // 0) split inputs to bf16 hi/lo
    int nx = BB * TT * CC;
    split_k<<<(nx / 4 + 255) / 256, 256>>>(x, xh, xl, nx);
    int nwq = CC * 3 * CC;
    split_k<<<(nwq / 4 + 255) / 256, 256>>>(Wqkv, wqh, wql, nwq);
    int nwo = CC * CC;
    split_k<<<(nwo / 4 + 255) / 256, 256>>>(Wo, woh, wol, nwo);

    // 1) qkv = x @ Wqkv  (tensor cores)
    dim3 g1(3 * CC / 128, BB * TT / 128);
    gemm3_k<<<g1, 256, GEMM_SMEM>>>(xh, xl, wqh, wql, qkv_p,
                                    BB * TT, 3 * CC, CC);
    // 2) rope + grouped scatter (split bf16)
    rope_k<<<(BB * HH * TT * 32) / 256, 256>>>(fc, fs);
    // 3) tensor-core block-causal attention (emits split-bf16 o)
    attn_k<<<BB * HH * GG * 4, 256, ATT_SMEM>>>();
    // 4) qb/kb/vb pools (tail of d_out)
    pool_k<<<3 * BB * HH * 7, 64>>>(qp, kp, vp, out);
    // 5) out = o @ Wo (head of d_out)
    dim3 g2(CC / 128, BB * TT / 128);
    gemm3_k<<<g2, 256, GEMM_SMEM>>>(obh, obl, woh, wol, out,
                                    BB * TT, CC, CC);
}